// round 8
// baseline (speedup 1.0000x reference)
#include <cuda_runtime.h>
#include <math.h>

#define THW 65536
#define C_ 32
#define KNN 8

// Scratch (allowed: __device__ globals, no allocation)
__device__ float g_stacked[256 * THW];   // 64 MB: [k*C+c][THW]
__device__ float g_x[C_ * THW];          // 8 MB : conv output [C][THW]
__device__ float g_wT[9 * 256 * 32];     // tf32-rounded conv weights [tap][ic][o]

__device__ __forceinline__ float tf32_rna(float v) {
    unsigned u;
    asm("cvt.rna.tf32.f32 %0, %1;" : "=r"(u) : "f"(v));
    return __uint_as_float(u);
}

// ---------------------------------------------------------------------------
// Stage 1: non-local kNN search + softmax-weighted stacking (unchanged, 614-base)
// ---------------------------------------------------------------------------
__global__ __launch_bounds__(128) void nl_stack_kernel(const float* __restrict__ vid) {
    int p = blockIdx.x * 128 + threadIdx.x;
    int t = p >> 14;
    int h = (p >> 7) & 127;
    int w = p & 127;

    float x[C_];
#pragma unroll
    for (int c = 0; c < C_; c++) x[c] = vid[c * THW + p];

    float bd[KNN];
    int   bq[KNN];
#pragma unroll
    for (int k = 0; k < KNN; k++) { bd[k] = 3.4e38f; bq[k] = 0; }

    for (int dt = -1; dt <= 1; dt++) {
        int ti = t + dt; ti = ti < 0 ? 0 : (ti > 3 ? 3 : ti);
        for (int dh = -4; dh <= 4; dh++) {
            int hi = h + dh; hi = hi < 0 ? 0 : (hi > 127 ? 127 : hi);
            for (int dw = -4; dw <= 4; dw++) {
                int wi = w + dw; wi = wi < 0 ? 0 : (wi > 127 ? 127 : wi);
                int q = ti * 16384 + hi * 128 + wi;
                float d0 = 0.0f, d1 = 0.0f, d2 = 0.0f, d3 = 0.0f;
#pragma unroll
                for (int c = 0; c < C_; c += 4) {
                    float a0 = x[c + 0] - vid[(c + 0) * THW + q];
                    float a1 = x[c + 1] - vid[(c + 1) * THW + q];
                    float a2 = x[c + 2] - vid[(c + 2) * THW + q];
                    float a3 = x[c + 3] - vid[(c + 3) * THW + q];
                    d0 = fmaf(a0, a0, d0);
                    d1 = fmaf(a1, a1, d1);
                    d2 = fmaf(a2, a2, d2);
                    d3 = fmaf(a3, a3, d3);
                }
                float d = (d0 + d1) + (d2 + d3);
                if (d < bd[KNN - 1]) {
                    int ins = KNN - 1;
#pragma unroll
                    for (int i = KNN - 2; i >= 0; i--) {
                        if (d < bd[i]) { bd[i + 1] = bd[i]; bq[i + 1] = bq[i]; ins = i; }
                    }
                    bd[ins] = d; bq[ins] = q;
                }
            }
        }
    }

    float e[KNN], s = 0.0f;
#pragma unroll
    for (int k = 0; k < KNN; k++) { e[k] = __expf(bd[0] - bd[k]); s += e[k]; }
    float inv = 1.0f / s;

#pragma unroll
    for (int k = 0; k < KNN; k++) {
        float wk = e[k] * inv;
        int q = bq[k];
#pragma unroll
        for (int c = 0; c < C_; c++) {
            g_stacked[(k * C_ + c) * THW + p] = vid[c * THW + q] * wk;
        }
    }
}

// ---------------------------------------------------------------------------
// Weight pre-transform (unchanged)
// ---------------------------------------------------------------------------
__global__ __launch_bounds__(128) void wT_kernel(const float* __restrict__ cw) {
    int i = blockIdx.x * 128 + threadIdx.x;
    int o = i & 31;
    int ic = (i >> 5) & 255;
    int tap = i >> 13;
    g_wT[i] = tf32_rna(cw[(o * 256 + ic) * 9 + tap]);
}

// ---------------------------------------------------------------------------
// Stage 2: conv as implicit GEMM on tf32 mma.sync.m16n8k8 (unchanged, 614-base)
// ---------------------------------------------------------------------------
__global__ __launch_bounds__(128) void conv_mma_kernel(const float* __restrict__ cb) {
    __shared__ float sA[64 * 40];
    __shared__ float sB[64 * 72];

    int tid = threadIdx.x;
    int lane = tid & 31, wid = tid >> 5;
    int lg = lane >> 2;
    int lk = lane & 3;

    int p0 = blockIdx.x * 64;
    int t = p0 >> 14, h = (p0 >> 7) & 127, wbase = p0 & 127;

    float c[2][2][4];
#pragma unroll
    for (int mt = 0; mt < 2; mt++)
#pragma unroll
        for (int nt = 0; nt < 2; nt++)
#pragma unroll
            for (int r = 0; r < 4; r++) c[mt][nt][r] = 0.0f;

    for (int tap = 0; tap < 9; tap++) {
        int kh = tap / 3 - 1, kw = tap % 3 - 1;
        int hp = h + kh;
        if (hp < 0 || hp > 127) continue;
        int base = t * 16384 + hp * 128 + wbase + kw;

        for (int ic0 = 0; ic0 < 256; ic0 += 64) {
            __syncthreads();
#pragma unroll
            for (int r = 0; r < 16; r++) {
                int idx = r * 128 + tid;
                int icl = idx >> 5, o = idx & 31;
                sA[icl * 40 + o] = g_wT[(tap * 256 + ic0 + icl) * 32 + o];
            }
#pragma unroll
            for (int r = 0; r < 32; r++) {
                int idx = r * 128 + tid;
                int icl = idx >> 6, n = idx & 63;
                int wq = wbase + n + kw;
                float v = 0.0f;
                if ((unsigned)wq < 128u)
                    v = g_stacked[(ic0 + icl) * THW + base + n];
                sB[icl * 72 + n] = tf32_rna(v);
            }
            __syncthreads();

#pragma unroll
            for (int kk = 0; kk < 8; kk++) {
                int kc = kk * 8;
                unsigned a[2][4], b[2][2];
#pragma unroll
                for (int mt = 0; mt < 2; mt++) {
                    int ob = mt * 16;
                    a[mt][0] = __float_as_uint(sA[(kc + lk) * 40 + ob + lg]);
                    a[mt][1] = __float_as_uint(sA[(kc + lk) * 40 + ob + lg + 8]);
                    a[mt][2] = __float_as_uint(sA[(kc + 4 + lk) * 40 + ob + lg]);
                    a[mt][3] = __float_as_uint(sA[(kc + 4 + lk) * 40 + ob + lg + 8]);
                }
#pragma unroll
                for (int nt = 0; nt < 2; nt++) {
                    int n0 = wid * 16 + nt * 8;
                    b[nt][0] = __float_as_uint(sB[(kc + lk) * 72 + n0 + lg]);
                    b[nt][1] = __float_as_uint(sB[(kc + 4 + lk) * 72 + n0 + lg]);
                }
#pragma unroll
                for (int mt = 0; mt < 2; mt++)
#pragma unroll
                    for (int nt = 0; nt < 2; nt++) {
                        asm volatile(
                            "mma.sync.aligned.m16n8k8.row.col.f32.tf32.tf32.f32 "
                            "{%0,%1,%2,%3}, {%4,%5,%6,%7}, {%8,%9}, {%0,%1,%2,%3};"
                            : "+f"(c[mt][nt][0]), "+f"(c[mt][nt][1]),
                              "+f"(c[mt][nt][2]), "+f"(c[mt][nt][3])
                            : "r"(a[mt][0]), "r"(a[mt][1]), "r"(a[mt][2]), "r"(a[mt][3]),
                              "r"(b[nt][0]), "r"(b[nt][1]));
                    }
            }
        }
    }

#pragma unroll
    for (int mt = 0; mt < 2; mt++) {
        int r0 = mt * 16 + lg;
        float b0 = cb[r0], b1 = cb[r0 + 8];
#pragma unroll
        for (int nt = 0; nt < 2; nt++) {
            int col = wid * 16 + nt * 8 + 2 * lk;
            float2 v0 = make_float2(c[mt][nt][0] + b0, c[mt][nt][1] + b0);
            float2 v1 = make_float2(c[mt][nt][2] + b1, c[mt][nt][3] + b1);
            *(float2*)&g_x[r0 * THW + p0 + col] = v0;
            *(float2*)&g_x[(r0 + 8) * THW + p0 + col] = v1;
        }
    }
}

// ---------------------------------------------------------------------------
// Stage 3: transformer. float4 weight loads in 8-output double-chunks
// (2 independent float4 acc chains), 2-pass attention, float4 K/V (pitch 36).
// ---------------------------------------------------------------------------
#define KV_PITCH 36

__device__ __forceinline__ float gelu_tanh(float a) {
    float inner = 0.7978845608028654f * fmaf(0.044715f * a, a * a, a);
    return 0.5f * a * (1.0f + tanhf(inner));
}

__global__ __launch_bounds__(128) void xf_kernel(
    const float* __restrict__ vid, float* __restrict__ out,
    const float* __restrict__ ln1_g, const float* __restrict__ ln1_b,
    const float* __restrict__ qkv_w, const float* __restrict__ qkv_b,
    const float* __restrict__ proj_w, const float* __restrict__ proj_b,
    const float* __restrict__ ln2_g, const float* __restrict__ ln2_b,
    const float* __restrict__ fc1_w, const float* __restrict__ fc1_b,
    const float* __restrict__ fc2_w, const float* __restrict__ fc2_b)
{
    extern __shared__ float sm[];
    float* s_qkvw = sm;                  // 3072
    float* s_qkvb = s_qkvw + 3072;       // 96
    float* s_projw = s_qkvb + 96;        // 1024
    float* s_projb = s_projw + 1024;     // 32
    float* s_fc1w = s_projb + 32;        // 2048
    float* s_fc1b = s_fc1w + 2048;       // 64
    float* s_fc2w = s_fc1b + 64;         // 2048
    float* s_fc2b = s_fc2w + 2048;       // 32
    float* s_g1 = s_fc2b + 32;           // 32
    float* s_b1 = s_g1 + 32;             // 32
    float* s_g2 = s_b1 + 32;             // 32
    float* s_b2 = s_g2 + 32;             // 32
    float* s_kv = s_b2 + 32;             // 2 windows x (2 x 64 x KV_PITCH)

    int tid = threadIdx.x;
    int wi = tid >> 6;
    int j = tid & 63;

    float* kbuf = s_kv + wi * (2 * 64 * KV_PITCH);
    float* vbuf = kbuf + 64 * KV_PITCH;

    int wg = blockIdx.x * 2 + wi;
    int t = wg >> 8, nh = (wg >> 4) & 15, nw = wg & 15;
    int h = nh * 8 + (j >> 3);
    int w = nw * 8 + (j & 7);
    int p = t * 16384 + h * 128 + w;

    float xr[32];
#pragma unroll
    for (int c = 0; c < 32; c++) xr[c] = g_x[c * THW + p];

    for (int L = 0; L < 2; L++) {
        __syncthreads();
        for (int idx = tid; idx < 3072; idx += 128) s_qkvw[idx] = qkv_w[L * 3072 + idx];
        for (int idx = tid; idx < 2048; idx += 128) {
            s_fc1w[idx] = fc1_w[L * 2048 + idx];
            s_fc2w[idx] = fc2_w[L * 2048 + idx];
        }
        for (int idx = tid; idx < 1024; idx += 128) s_projw[idx] = proj_w[L * 1024 + idx];
        if (tid < 96) s_qkvb[tid] = qkv_b[L * 96 + tid];
        if (tid < 64) s_fc1b[tid] = fc1_b[L * 64 + tid];
        if (tid < 32) {
            s_projb[tid] = proj_b[L * 32 + tid];
            s_fc2b[tid] = fc2_b[L * 32 + tid];
            s_g1[tid] = ln1_g[L * 32 + tid];
            s_b1[tid] = ln1_b[L * 32 + tid];
            s_g2[tid] = ln2_g[L * 32 + tid];
            s_b2[tid] = ln2_b[L * 32 + tid];
        }
        __syncthreads();

        // ---- LN1 ----
        float mu = 0.0f;
#pragma unroll
        for (int c = 0; c < 32; c++) mu += xr[c];
        mu *= 0.03125f;
        float var = 0.0f;
#pragma unroll
        for (int c = 0; c < 32; c++) { float d = xr[c] - mu; var = fmaf(d, d, var); }
        var *= 0.03125f;
        float rstd = rsqrtf(var + 1e-5f);
        float hv[32];
#pragma unroll
        for (int c = 0; c < 32; c++) hv[c] = (xr[c] - mu) * rstd * s_g1[c] + s_b1[c];

        const float scale = 0.3535533905932738f;   // 8^-0.5
        float q[32];

        // ---- Q: 8-output double-chunks ----
#pragma unroll
        for (int j0 = 0; j0 < 32; j0 += 8) {
            float4 a0 = *(const float4*)&s_qkvb[j0];
            float4 a1 = *(const float4*)&s_qkvb[j0 + 4];
#pragma unroll
            for (int c = 0; c < 32; c++) {
                float hc = hv[c];
                float4 w0 = *(const float4*)&s_qkvw[c * 96 + j0];
                float4 w1 = *(const float4*)&s_qkvw[c * 96 + j0 + 4];
                a0.x = fmaf(hc, w0.x, a0.x); a0.y = fmaf(hc, w0.y, a0.y);
                a0.z = fmaf(hc, w0.z, a0.z); a0.w = fmaf(hc, w0.w, a0.w);
                a1.x = fmaf(hc, w1.x, a1.x); a1.y = fmaf(hc, w1.y, a1.y);
                a1.z = fmaf(hc, w1.z, a1.z); a1.w = fmaf(hc, w1.w, a1.w);
            }
            q[j0 + 0] = a0.x * scale; q[j0 + 1] = a0.y * scale;
            q[j0 + 2] = a0.z * scale; q[j0 + 3] = a0.w * scale;
            q[j0 + 4] = a1.x * scale; q[j0 + 5] = a1.y * scale;
            q[j0 + 6] = a1.z * scale; q[j0 + 7] = a1.w * scale;
        }
        // ---- K ----
#pragma unroll
        for (int j0 = 0; j0 < 32; j0 += 8) {
            float4 a0 = *(const float4*)&s_qkvb[32 + j0];
            float4 a1 = *(const float4*)&s_qkvb[32 + j0 + 4];
#pragma unroll
            for (int c = 0; c < 32; c++) {
                float hc = hv[c];
                float4 w0 = *(const float4*)&s_qkvw[c * 96 + 32 + j0];
                float4 w1 = *(const float4*)&s_qkvw[c * 96 + 32 + j0 + 4];
                a0.x = fmaf(hc, w0.x, a0.x); a0.y = fmaf(hc, w0.y, a0.y);
                a0.z = fmaf(hc, w0.z, a0.z); a0.w = fmaf(hc, w0.w, a0.w);
                a1.x = fmaf(hc, w1.x, a1.x); a1.y = fmaf(hc, w1.y, a1.y);
                a1.z = fmaf(hc, w1.z, a1.z); a1.w = fmaf(hc, w1.w, a1.w);
            }
            *(float4*)&kbuf[j * KV_PITCH + j0] = a0;
            *(float4*)&kbuf[j * KV_PITCH + j0 + 4] = a1;
        }
        // ---- V ----
#pragma unroll
        for (int j0 = 0; j0 < 32; j0 += 8) {
            float4 a0 = *(const float4*)&s_qkvb[64 + j0];
            float4 a1 = *(const float4*)&s_qkvb[64 + j0 + 4];
#pragma unroll
            for (int c = 0; c < 32; c++) {
                float hc = hv[c];
                float4 w0 = *(const float4*)&s_qkvw[c * 96 + 64 + j0];
                float4 w1 = *(const float4*)&s_qkvw[c * 96 + 64 + j0 + 4];
                a0.x = fmaf(hc, w0.x, a0.x); a0.y = fmaf(hc, w0.y, a0.y);
                a0.z = fmaf(hc, w0.z, a0.z); a0.w = fmaf(hc, w0.w, a0.w);
                a1.x = fmaf(hc, w1.x, a1.x); a1.y = fmaf(hc, w1.y, a1.y);
                a1.z = fmaf(hc, w1.z, a1.z); a1.w = fmaf(hc, w1.w, a1.w);
            }
            *(float4*)&vbuf[j * KV_PITCH + j0] = a0;
            *(float4*)&vbuf[j * KV_PITCH + j0 + 4] = a1;
        }
        __syncthreads();

        // ---- attention: 2-pass (true-max) softmax, float4 K/V ----
        float ov[32];
#pragma unroll
        for (int hh = 0; hh < 4; hh++) {
            const int base = hh * 8;
            // pass 1: max with 2 partial chains
            float mx0 = -1e30f, mx1 = -1e30f;
            for (int kk = 0; kk < 64; kk += 2) {
                const float4 ka0 = *(const float4*)&kbuf[kk * KV_PITCH + base];
                const float4 ka1 = *(const float4*)&kbuf[kk * KV_PITCH + base + 4];
                const float4 kb0 = *(const float4*)&kbuf[(kk + 1) * KV_PITCH + base];
                const float4 kb1 = *(const float4*)&kbuf[(kk + 1) * KV_PITCH + base + 4];
                float sa = q[base] * ka0.x, sb = q[base] * kb0.x;
                sa = fmaf(q[base + 1], ka0.y, sa); sb = fmaf(q[base + 1], kb0.y, sb);
                sa = fmaf(q[base + 2], ka0.z, sa); sb = fmaf(q[base + 2], kb0.z, sb);
                sa = fmaf(q[base + 3], ka0.w, sa); sb = fmaf(q[base + 3], kb0.w, sb);
                sa = fmaf(q[base + 4], ka1.x, sa); sb = fmaf(q[base + 4], kb1.x, sb);
                sa = fmaf(q[base + 5], ka1.y, sa); sb = fmaf(q[base + 5], kb1.y, sb);
                sa = fmaf(q[base + 6], ka1.z, sa); sb = fmaf(q[base + 6], kb1.z, sb);
                sa = fmaf(q[base + 7], ka1.w, sa); sb = fmaf(q[base + 7], kb1.w, sb);
                mx0 = fmaxf(mx0, sa);
                mx1 = fmaxf(mx1, sb);
            }
            float mx = fmaxf(mx0, mx1);
            // pass 2: exp + accumulate (9 independent chains)
            float sum = 0.0f;
            float o0 = 0, o1 = 0, o2 = 0, o3 = 0, o4 = 0, o5 = 0, o6 = 0, o7 = 0;
            for (int kk = 0; kk < 64; kk++) {
                const float4 k0 = *(const float4*)&kbuf[kk * KV_PITCH + base];
                const float4 k1 = *(const float4*)&kbuf[kk * KV_PITCH + base + 4];
                float s = q[base] * k0.x;
                s = fmaf(q[base + 1], k0.y, s);
                s = fmaf(q[base + 2], k0.z, s);
                s = fmaf(q[base + 3], k0.w, s);
                s = fmaf(q[base + 4], k1.x, s);
                s = fmaf(q[base + 5], k1.y, s);
                s = fmaf(q[base + 6], k1.z, s);
                s = fmaf(q[base + 7], k1.w, s);
                float e = __expf(s - mx);
                sum += e;
                const float4 v0 = *(const float4*)&vbuf[kk * KV_PITCH + base];
                const float4 v1 = *(const float4*)&vbuf[kk * KV_PITCH + base + 4];
                o0 = fmaf(e, v0.x, o0); o1 = fmaf(e, v0.y, o1);
                o2 = fmaf(e, v0.z, o2); o3 = fmaf(e, v0.w, o3);
                o4 = fmaf(e, v1.x, o4); o5 = fmaf(e, v1.y, o5);
                o6 = fmaf(e, v1.z, o6); o7 = fmaf(e, v1.w, o7);
            }
            float inv = 1.0f / sum;
            ov[base + 0] = o0 * inv; ov[base + 1] = o1 * inv;
            ov[base + 2] = o2 * inv; ov[base + 3] = o3 * inv;
            ov[base + 4] = o4 * inv; ov[base + 5] = o5 * inv;
            ov[base + 6] = o6 * inv; ov[base + 7] = o7 * inv;
        }

        // ---- proj + residual: float4 weights, 32 independent accumulators ----
        float pr[32];
#pragma unroll
        for (int c = 0; c < 32; c++) pr[c] = 0.0f;
#pragma unroll
        for (int u = 0; u < 32; u++) {
            float o = ov[u];
#pragma unroll
            for (int c0 = 0; c0 < 32; c0 += 4) {
                float4 wv = *(const float4*)&s_projw[u * 32 + c0];
                pr[c0 + 0] = fmaf(o, wv.x, pr[c0 + 0]);
                pr[c0 + 1] = fmaf(o, wv.y, pr[c0 + 1]);
                pr[c0 + 2] = fmaf(o, wv.z, pr[c0 + 2]);
                pr[c0 + 3] = fmaf(o, wv.w, pr[c0 + 3]);
            }
        }
#pragma unroll
        for (int c = 0; c < 32; c++) xr[c] += pr[c] + s_projb[c];

        // ---- LN2 ----
        mu = 0.0f;
#pragma unroll
        for (int c = 0; c < 32; c++) mu += xr[c];
        mu *= 0.03125f;
        var = 0.0f;
#pragma unroll
        for (int c = 0; c < 32; c++) { float d = xr[c] - mu; var = fmaf(d, d, var); }
        var *= 0.03125f;
        rstd = rsqrtf(var + 1e-5f);
#pragma unroll
        for (int c = 0; c < 32; c++) hv[c] = (xr[c] - mu) * rstd * s_g2[c] + s_b2[c];

        // ---- MLP: fc1 in 8-output double-chunks, fc2 into acc[32] ----
        float acc[32];
#pragma unroll
        for (int c = 0; c < 32; c++) acc[c] = 0.0f;
#pragma unroll
        for (int u0 = 0; u0 < 64; u0 += 8) {
            float4 a0 = *(const float4*)&s_fc1b[u0];
            float4 a1 = *(const float4*)&s_fc1b[u0 + 4];
#pragma unroll
            for (int c = 0; c < 32; c++) {
                float hc = hv[c];
                float4 w0 = *(const float4*)&s_fc1w[c * 64 + u0];
                float4 w1 = *(const float4*)&s_fc1w[c * 64 + u0 + 4];
                a0.x = fmaf(hc, w0.x, a0.x); a0.y = fmaf(hc, w0.y, a0.y);
                a0.z = fmaf(hc, w0.z, a0.z); a0.w = fmaf(hc, w0.w, a0.w);
                a1.x = fmaf(hc, w1.x, a1.x); a1.y = fmaf(hc, w1.y, a1.y);
                a1.z = fmaf(hc, w1.z, a1.z); a1.w = fmaf(hc, w1.w, a1.w);
            }
            float g[8];
            g[0] = gelu_tanh(a0.x); g[1] = gelu_tanh(a0.y);
            g[2] = gelu_tanh(a0.z); g[3] = gelu_tanh(a0.w);
            g[4] = gelu_tanh(a1.x); g[5] = gelu_tanh(a1.y);
            g[6] = gelu_tanh(a1.z); g[7] = gelu_tanh(a1.w);
#pragma unroll
            for (int i = 0; i < 8; i++) {
                float gi = g[i];
#pragma unroll
                for (int c0 = 0; c0 < 32; c0 += 4) {
                    float4 wv = *(const float4*)&s_fc2w[(u0 + i) * 32 + c0];
                    acc[c0 + 0] = fmaf(gi, wv.x, acc[c0 + 0]);
                    acc[c0 + 1] = fmaf(gi, wv.y, acc[c0 + 1]);
                    acc[c0 + 2] = fmaf(gi, wv.z, acc[c0 + 2]);
                    acc[c0 + 3] = fmaf(gi, wv.w, acc[c0 + 3]);
                }
            }
        }
#pragma unroll
        for (int c = 0; c < 32; c++) xr[c] += acc[c] + s_fc2b[c];
    }

    // final residual with original video
#pragma unroll
    for (int c = 0; c < 32; c++) out[c * THW + p] = vid[c * THW + p] + xr[c];
}

// ---------------------------------------------------------------------------
extern "C" void kernel_launch(void* const* d_in, const int* in_sizes, int n_in,
                              void* d_out, int out_size) {
    const float* vid    = (const float*)d_in[0];
    const float* conv_w = (const float*)d_in[1];
    const float* conv_b = (const float*)d_in[2];
    const float* ln1_g  = (const float*)d_in[3];
    const float* ln1_b  = (const float*)d_in[4];
    const float* qkv_w  = (const float*)d_in[5];
    const float* qkv_b  = (const float*)d_in[6];
    const float* proj_w = (const float*)d_in[7];
    const float* proj_b = (const float*)d_in[8];
    const float* ln2_g  = (const float*)d_in[9];
    const float* ln2_b  = (const float*)d_in[10];
    const float* fc1_w  = (const float*)d_in[11];
    const float* fc1_b  = (const float*)d_in[12];
    const float* fc2_w  = (const float*)d_in[13];
    const float* fc2_b  = (const float*)d_in[14];
    float* out = (float*)d_out;

    nl_stack_kernel<<<512, 128>>>(vid);
    wT_kernel<<<576, 128>>>(conv_w);
    conv_mma_kernel<<<1024, 128>>>(conv_b);

    const int smem_bytes = (8544 + 2 * 2 * 64 * KV_PITCH) * (int)sizeof(float);  // 71040
    cudaFuncSetAttribute(xf_kernel, cudaFuncAttributeMaxDynamicSharedMemorySize, smem_bytes);
    xf_kernel<<<512, 128, smem_bytes>>>(vid, out,
                                        ln1_g, ln1_b, qkv_w, qkv_b, proj_w, proj_b,
                                        ln2_g, ln2_b, fc1_w, fc1_b, fc2_w, fc2_b);
}

// round 9
// speedup vs baseline: 1.1033x; 1.1033x over previous
#include <cuda_runtime.h>
#include <math.h>

#define THW 65536
#define C_ 32
#define KNN 8

// Scratch (allowed: __device__ globals, no allocation)
__device__ float g_stacked[256 * THW];   // 64 MB: [k*C+c][THW]
__device__ float g_x[C_ * THW];          // 8 MB : conv output [C][THW]
__device__ float g_wT[9 * 256 * 32];     // tf32-rounded conv weights [tap][ic][o]

__device__ __forceinline__ float tf32_rna(float v) {
    unsigned u;
    asm("cvt.rna.tf32.f32 %0, %1;" : "=r"(u) : "f"(v));
    return __uint_as_float(u);
}

// ---------------------------------------------------------------------------
// Stage 1: non-local kNN search, 2 threads per voxel (lane pair).
// Lane A scans offsets 0..121, lane B 122..242; each keeps a sorted top-8;
// shfl exchange + static bitonic merge of 16 -> global top-8.
// ---------------------------------------------------------------------------
__global__ __launch_bounds__(128) void nl_stack_kernel(const float* __restrict__ vid) {
    int gtid = blockIdx.x * 128 + threadIdx.x;
    int p = gtid >> 1;           // voxel
    int half = gtid & 1;         // 0: offsets 0..121, 1: 122..242
    int t = p >> 14;
    int h = (p >> 7) & 127;
    int w = p & 127;

    float x[C_];
#pragma unroll
    for (int c = 0; c < C_; c++) x[c] = vid[c * THW + p];

    float bd[KNN];
    int   bq[KNN];
#pragma unroll
    for (int k = 0; k < KNN; k++) { bd[k] = 3.4e38f; bq[k] = 0; }

    int obase = half ? 122 : 0;
    int niter = half ? 121 : 122;
    for (int i = 0; i < niter; i++) {
        int o = obase + i;                 // flat offset index, meshgrid order
        int dt = o / 81;                   // 0..2
        int r  = o - dt * 81;
        int dh = r / 9;                    // 0..8
        int dw = r - dh * 9;               // 0..8
        int ti = t + dt - 1; ti = ti < 0 ? 0 : (ti > 3 ? 3 : ti);
        int hi = h + dh - 4; hi = hi < 0 ? 0 : (hi > 127 ? 127 : hi);
        int wi = w + dw - 4; wi = wi < 0 ? 0 : (wi > 127 ? 127 : wi);
        int q = ti * 16384 + hi * 128 + wi;
        float d0 = 0.0f, d1 = 0.0f, d2 = 0.0f, d3 = 0.0f;
#pragma unroll
        for (int c = 0; c < C_; c += 4) {
            float a0 = x[c + 0] - vid[(c + 0) * THW + q];
            float a1 = x[c + 1] - vid[(c + 1) * THW + q];
            float a2 = x[c + 2] - vid[(c + 2) * THW + q];
            float a3 = x[c + 3] - vid[(c + 3) * THW + q];
            d0 = fmaf(a0, a0, d0);
            d1 = fmaf(a1, a1, d1);
            d2 = fmaf(a2, a2, d2);
            d3 = fmaf(a3, a3, d3);
        }
        float d = (d0 + d1) + (d2 + d3);
        if (d < bd[KNN - 1]) {
            int ins = KNN - 1;
#pragma unroll
            for (int k = KNN - 2; k >= 0; k--) {
                if (d < bd[k]) { bd[k + 1] = bd[k]; bq[k + 1] = bq[k]; ins = k; }
            }
            bd[ins] = d; bq[ins] = q;
        }
    }

    // exchange partner's sorted top-8 (reversed -> bitonic 16-sequence)
    float md[16]; int mq[16];
#pragma unroll
    for (int k = 0; k < 8; k++) { md[k] = bd[k]; mq[k] = bq[k]; }
#pragma unroll
    for (int k = 0; k < 8; k++) {
        md[8 + k] = __shfl_xor_sync(0xffffffffu, bd[7 - k], 1);
        mq[8 + k] = __shfl_xor_sync(0xffffffffu, bq[7 - k], 1);
    }
    // bitonic merge: fully sort 16 ascending (static indices only)
#pragma unroll
    for (int dlt = 8; dlt >= 1; dlt >>= 1) {
#pragma unroll
        for (int i = 0; i < 16; i++) {
            if ((i & dlt) == 0) {
                float da = md[i], db = md[i + dlt];
                int   qa = mq[i], qb = mq[i + dlt];
                bool sw = db < da;
                md[i]       = sw ? db : da;
                md[i + dlt] = sw ? da : db;
                mq[i]       = sw ? qb : qa;
                mq[i + dlt] = sw ? qa : qb;
            }
        }
    }

    // softmax(-d) over merged top-8; md[0] = min distance
    float e0 = __expf(md[0] - md[0]), e1 = __expf(md[0] - md[1]);
    float e2 = __expf(md[0] - md[2]), e3 = __expf(md[0] - md[3]);
    float e4 = __expf(md[0] - md[4]), e5 = __expf(md[0] - md[5]);
    float e6 = __expf(md[0] - md[6]), e7 = __expf(md[0] - md[7]);
    float sum = ((e0 + e1) + (e2 + e3)) + ((e4 + e5) + (e6 + e7));
    float inv = 1.0f / sum;

    // this lane writes 4 of the 8 k-slices (A: 0..3, B: 4..7), branch-free sel
    int kbase = half * 4;
#pragma unroll
    for (int kk = 0; kk < 4; kk++) {
        float ek;
        int qk;
        switch (kk) {   // static pairs; half-select only
            case 0: ek = half ? e4 : e0; qk = half ? mq[4] : mq[0]; break;
            case 1: ek = half ? e5 : e1; qk = half ? mq[5] : mq[1]; break;
            case 2: ek = half ? e6 : e2; qk = half ? mq[6] : mq[2]; break;
            default: ek = half ? e7 : e3; qk = half ? mq[7] : mq[3]; break;
        }
        float wk = ek * inv;
#pragma unroll
        for (int c = 0; c < C_; c++) {
            g_stacked[((kbase + kk) * C_ + c) * THW + p] = vid[c * THW + qk] * wk;
        }
    }
}

// ---------------------------------------------------------------------------
// Weight pre-transform (unchanged)
// ---------------------------------------------------------------------------
__global__ __launch_bounds__(128) void wT_kernel(const float* __restrict__ cw) {
    int i = blockIdx.x * 128 + threadIdx.x;
    int o = i & 31;
    int ic = (i >> 5) & 255;
    int tap = i >> 13;
    g_wT[i] = tf32_rna(cw[(o * 256 + ic) * 9 + tap]);
}

// ---------------------------------------------------------------------------
// Stage 2: conv as implicit GEMM on tf32 mma.sync.m16n8k8 (unchanged, 614-base)
// ---------------------------------------------------------------------------
__global__ __launch_bounds__(128) void conv_mma_kernel(const float* __restrict__ cb) {
    __shared__ float sA[64 * 40];
    __shared__ float sB[64 * 72];

    int tid = threadIdx.x;
    int lane = tid & 31, wid = tid >> 5;
    int lg = lane >> 2;
    int lk = lane & 3;

    int p0 = blockIdx.x * 64;
    int t = p0 >> 14, h = (p0 >> 7) & 127, wbase = p0 & 127;

    float c[2][2][4];
#pragma unroll
    for (int mt = 0; mt < 2; mt++)
#pragma unroll
        for (int nt = 0; nt < 2; nt++)
#pragma unroll
            for (int r = 0; r < 4; r++) c[mt][nt][r] = 0.0f;

    for (int tap = 0; tap < 9; tap++) {
        int kh = tap / 3 - 1, kw = tap % 3 - 1;
        int hp = h + kh;
        if (hp < 0 || hp > 127) continue;
        int base = t * 16384 + hp * 128 + wbase + kw;

        for (int ic0 = 0; ic0 < 256; ic0 += 64) {
            __syncthreads();
#pragma unroll
            for (int r = 0; r < 16; r++) {
                int idx = r * 128 + tid;
                int icl = idx >> 5, o = idx & 31;
                sA[icl * 40 + o] = g_wT[(tap * 256 + ic0 + icl) * 32 + o];
            }
#pragma unroll
            for (int r = 0; r < 32; r++) {
                int idx = r * 128 + tid;
                int icl = idx >> 6, n = idx & 63;
                int wq = wbase + n + kw;
                float v = 0.0f;
                if ((unsigned)wq < 128u)
                    v = g_stacked[(ic0 + icl) * THW + base + n];
                sB[icl * 72 + n] = tf32_rna(v);
            }
            __syncthreads();

#pragma unroll
            for (int kk = 0; kk < 8; kk++) {
                int kc = kk * 8;
                unsigned a[2][4], b[2][2];
#pragma unroll
                for (int mt = 0; mt < 2; mt++) {
                    int ob = mt * 16;
                    a[mt][0] = __float_as_uint(sA[(kc + lk) * 40 + ob + lg]);
                    a[mt][1] = __float_as_uint(sA[(kc + lk) * 40 + ob + lg + 8]);
                    a[mt][2] = __float_as_uint(sA[(kc + 4 + lk) * 40 + ob + lg]);
                    a[mt][3] = __float_as_uint(sA[(kc + 4 + lk) * 40 + ob + lg + 8]);
                }
#pragma unroll
                for (int nt = 0; nt < 2; nt++) {
                    int n0 = wid * 16 + nt * 8;
                    b[nt][0] = __float_as_uint(sB[(kc + lk) * 72 + n0 + lg]);
                    b[nt][1] = __float_as_uint(sB[(kc + 4 + lk) * 72 + n0 + lg]);
                }
#pragma unroll
                for (int mt = 0; mt < 2; mt++)
#pragma unroll
                    for (int nt = 0; nt < 2; nt++) {
                        asm volatile(
                            "mma.sync.aligned.m16n8k8.row.col.f32.tf32.tf32.f32 "
                            "{%0,%1,%2,%3}, {%4,%5,%6,%7}, {%8,%9}, {%0,%1,%2,%3};"
                            : "+f"(c[mt][nt][0]), "+f"(c[mt][nt][1]),
                              "+f"(c[mt][nt][2]), "+f"(c[mt][nt][3])
                            : "r"(a[mt][0]), "r"(a[mt][1]), "r"(a[mt][2]), "r"(a[mt][3]),
                              "r"(b[nt][0]), "r"(b[nt][1]));
                    }
            }
        }
    }

#pragma unroll
    for (int mt = 0; mt < 2; mt++) {
        int r0 = mt * 16 + lg;
        float b0 = cb[r0], b1 = cb[r0 + 8];
#pragma unroll
        for (int nt = 0; nt < 2; nt++) {
            int col = wid * 16 + nt * 8 + 2 * lk;
            float2 v0 = make_float2(c[mt][nt][0] + b0, c[mt][nt][1] + b0);
            float2 v1 = make_float2(c[mt][nt][2] + b1, c[mt][nt][3] + b1);
            *(float2*)&g_x[r0 * THW + p0 + col] = v0;
            *(float2*)&g_x[(r0 + 8) * THW + p0 + col] = v1;
        }
    }
}

// ---------------------------------------------------------------------------
// Stage 3: transformer — EXACT round-5 scalar version (measured 252us best).
// ---------------------------------------------------------------------------
__device__ __forceinline__ float gelu_tanh(float a) {
    float inner = 0.7978845608028654f * fmaf(0.044715f * a, a * a, a);
    return 0.5f * a * (1.0f + tanhf(inner));
}

__global__ __launch_bounds__(128) void xf_kernel(
    const float* __restrict__ vid, float* __restrict__ out,
    const float* __restrict__ ln1_g, const float* __restrict__ ln1_b,
    const float* __restrict__ qkv_w, const float* __restrict__ qkv_b,
    const float* __restrict__ proj_w, const float* __restrict__ proj_b,
    const float* __restrict__ ln2_g, const float* __restrict__ ln2_b,
    const float* __restrict__ fc1_w, const float* __restrict__ fc1_b,
    const float* __restrict__ fc2_w, const float* __restrict__ fc2_b)
{
    extern __shared__ float sm[];
    float* s_qkvw = sm;                  // 3072
    float* s_qkvb = s_qkvw + 3072;       // 96
    float* s_projw = s_qkvb + 96;        // 1024
    float* s_projb = s_projw + 1024;     // 32
    float* s_fc1w = s_projb + 32;        // 2048
    float* s_fc1b = s_fc1w + 2048;       // 64
    float* s_fc2w = s_fc1b + 64;         // 2048
    float* s_fc2b = s_fc2w + 2048;       // 32
    float* s_g1 = s_fc2b + 32;           // 32
    float* s_b1 = s_g1 + 32;             // 32
    float* s_g2 = s_b1 + 32;             // 32
    float* s_b2 = s_g2 + 32;             // 32
    float* s_kv = s_b2 + 32;             // 2 windows x (2 x 64 x 33)

    int tid = threadIdx.x;
    int wi = tid >> 6;
    int j = tid & 63;

    float* kbuf = s_kv + wi * (2 * 64 * 33);
    float* vbuf = kbuf + 64 * 33;

    int wg = blockIdx.x * 2 + wi;
    int t = wg >> 8, nh = (wg >> 4) & 15, nw = wg & 15;
    int h = nh * 8 + (j >> 3);
    int w = nw * 8 + (j & 7);
    int p = t * 16384 + h * 128 + w;

    float xr[32];
#pragma unroll
    for (int c = 0; c < 32; c++) xr[c] = g_x[c * THW + p];

    for (int L = 0; L < 2; L++) {
        __syncthreads();
        for (int idx = tid; idx < 3072; idx += 128) s_qkvw[idx] = qkv_w[L * 3072 + idx];
        for (int idx = tid; idx < 2048; idx += 128) {
            s_fc1w[idx] = fc1_w[L * 2048 + idx];
            s_fc2w[idx] = fc2_w[L * 2048 + idx];
        }
        for (int idx = tid; idx < 1024; idx += 128) s_projw[idx] = proj_w[L * 1024 + idx];
        if (tid < 96) s_qkvb[tid] = qkv_b[L * 96 + tid];
        if (tid < 64) s_fc1b[tid] = fc1_b[L * 64 + tid];
        if (tid < 32) {
            s_projb[tid] = proj_b[L * 32 + tid];
            s_fc2b[tid] = fc2_b[L * 32 + tid];
            s_g1[tid] = ln1_g[L * 32 + tid];
            s_b1[tid] = ln1_b[L * 32 + tid];
            s_g2[tid] = ln2_g[L * 32 + tid];
            s_b2[tid] = ln2_b[L * 32 + tid];
        }
        __syncthreads();

        float mu = 0.0f;
#pragma unroll
        for (int c = 0; c < 32; c++) mu += xr[c];
        mu *= 0.03125f;
        float var = 0.0f;
#pragma unroll
        for (int c = 0; c < 32; c++) { float d = xr[c] - mu; var = fmaf(d, d, var); }
        var *= 0.03125f;
        float rstd = rsqrtf(var + 1e-5f);
        float hv[32];
#pragma unroll
        for (int c = 0; c < 32; c++) hv[c] = (xr[c] - mu) * rstd * s_g1[c] + s_b1[c];

        float q[32];
#pragma unroll
        for (int jq = 0; jq < 32; jq++) {
            float s = s_qkvb[jq];
#pragma unroll
            for (int c = 0; c < 32; c++) s = fmaf(hv[c], s_qkvw[c * 96 + jq], s);
            q[jq] = s;
        }
        for (int jk = 0; jk < 32; jk++) {
            float s = s_qkvb[32 + jk];
#pragma unroll
            for (int c = 0; c < 32; c++) s = fmaf(hv[c], s_qkvw[c * 96 + 32 + jk], s);
            kbuf[j * 33 + jk] = s;
        }
        for (int jv = 0; jv < 32; jv++) {
            float s = s_qkvb[64 + jv];
#pragma unroll
            for (int c = 0; c < 32; c++) s = fmaf(hv[c], s_qkvw[c * 96 + 64 + jv], s);
            vbuf[j * 33 + jv] = s;
        }
        __syncthreads();

        float ov[32];
#pragma unroll
        for (int c = 0; c < 32; c++) ov[c] = 0.0f;
        const float scale = 0.3535533905932738f;
#pragma unroll
        for (int hh = 0; hh < 4; hh++) {
            const int base = hh * 8;
            float mx = -1e30f;
            for (int kk = 0; kk < 64; kk++) {
                float s = 0.0f;
#pragma unroll
                for (int d = 0; d < 8; d++) s = fmaf(q[base + d], kbuf[kk * 33 + base + d], s);
                mx = fmaxf(mx, s * scale);
            }
            float sum = 0.0f;
            for (int kk = 0; kk < 64; kk++) {
                float s = 0.0f;
#pragma unroll
                for (int d = 0; d < 8; d++) s = fmaf(q[base + d], kbuf[kk * 33 + base + d], s);
                sum += __expf(s * scale - mx);
            }
            float inv = 1.0f / sum;
            for (int kk = 0; kk < 64; kk++) {
                float s = 0.0f;
#pragma unroll
                for (int d = 0; d < 8; d++) s = fmaf(q[base + d], kbuf[kk * 33 + base + d], s);
                float pw = __expf(s * scale - mx) * inv;
#pragma unroll
                for (int d = 0; d < 8; d++) ov[base + d] = fmaf(pw, vbuf[kk * 33 + base + d], ov[base + d]);
            }
        }

#pragma unroll
        for (int c = 0; c < 32; c++) {
            float s = s_projb[c];
#pragma unroll
            for (int u = 0; u < 32; u++) s = fmaf(ov[u], s_projw[u * 32 + c], s);
            xr[c] += s;
        }

        mu = 0.0f;
#pragma unroll
        for (int c = 0; c < 32; c++) mu += xr[c];
        mu *= 0.03125f;
        var = 0.0f;
#pragma unroll
        for (int c = 0; c < 32; c++) { float d = xr[c] - mu; var = fmaf(d, d, var); }
        var *= 0.03125f;
        rstd = rsqrtf(var + 1e-5f);
#pragma unroll
        for (int c = 0; c < 32; c++) hv[c] = (xr[c] - mu) * rstd * s_g2[c] + s_b2[c];

        float acc[32];
#pragma unroll
        for (int c = 0; c < 32; c++) acc[c] = 0.0f;
        for (int u = 0; u < 64; u++) {
            float a = s_fc1b[u];
#pragma unroll
            for (int c = 0; c < 32; c++) a = fmaf(hv[c], s_fc1w[c * 64 + u], a);
            float g = gelu_tanh(a);
#pragma unroll
            for (int c = 0; c < 32; c++) acc[c] = fmaf(g, s_fc2w[u * 32 + c], acc[c]);
        }
#pragma unroll
        for (int c = 0; c < 32; c++) xr[c] += acc[c] + s_fc2b[c];
    }

#pragma unroll
    for (int c = 0; c < 32; c++) out[c * THW + p] = vid[c * THW + p] + xr[c];
}

// ---------------------------------------------------------------------------
extern "C" void kernel_launch(void* const* d_in, const int* in_sizes, int n_in,
                              void* d_out, int out_size) {
    const float* vid    = (const float*)d_in[0];
    const float* conv_w = (const float*)d_in[1];
    const float* conv_b = (const float*)d_in[2];
    const float* ln1_g  = (const float*)d_in[3];
    const float* ln1_b  = (const float*)d_in[4];
    const float* qkv_w  = (const float*)d_in[5];
    const float* qkv_b  = (const float*)d_in[6];
    const float* proj_w = (const float*)d_in[7];
    const float* proj_b = (const float*)d_in[8];
    const float* ln2_g  = (const float*)d_in[9];
    const float* ln2_b  = (const float*)d_in[10];
    const float* fc1_w  = (const float*)d_in[11];
    const float* fc1_b  = (const float*)d_in[12];
    const float* fc2_w  = (const float*)d_in[13];
    const float* fc2_b  = (const float*)d_in[14];
    float* out = (float*)d_out;

    nl_stack_kernel<<<1024, 128>>>(vid);      // 2 threads per voxel
    wT_kernel<<<576, 128>>>(conv_w);
    conv_mma_kernel<<<1024, 128>>>(conv_b);

    const int smem_bytes = (8544 + 2 * 2 * 64 * 33) * (int)sizeof(float);  // 67968
    cudaFuncSetAttribute(xf_kernel, cudaFuncAttributeMaxDynamicSharedMemorySize, smem_bytes);
    xf_kernel<<<512, 128, smem_bytes>>>(vid, out,
                                        ln1_g, ln1_b, qkv_w, qkv_b, proj_w, proj_b,
                                        ln2_g, ln2_b, fc1_w, fc1_b, fc2_w, fc2_b);
}